// round 2
// baseline (speedup 1.0000x reference)
#include <cuda_runtime.h>
#include <math.h>

// Problem constants
#define SEQ   1024          // B*H*W = 4*16*16
#define TT    64            // T
#define DD    256           // D
#define NHH   8
#define DH    32            // D / NH
#define MROWS (SEQ * TT)    // 65536

// Scratch (no cudaMalloc allowed)
__device__ float g_q[(size_t)MROWS * DD];
__device__ float g_k[(size_t)MROWS * DD];
__device__ float g_v[(size_t)MROWS * DD];
__device__ float g_ctx[(size_t)MROWS * DD];

// ---------------------------------------------------------------------------
// GEMM: C[M, 256] = A[M, 256] @ W[256, 256] + bias[256]
// BM=128, BN=128, BK=8; 256 threads; 8x8 per thread.
// ---------------------------------------------------------------------------
#define BM 128
#define BN 128
#define BK 8

__global__ __launch_bounds__(256) void gemm_bias_kernel(
    const float* __restrict__ A, const float* __restrict__ W,
    const float* __restrict__ bias, float* __restrict__ C)
{
    __shared__ float As[BK][BM];
    __shared__ float Ws[BK][BN];

    const int tid = threadIdx.x;
    const int tx  = tid & 15;   // N direction (16 threads * 8 cols = 128)
    const int ty  = tid >> 4;   // M direction (16 threads * 8 rows = 128)
    const int rowBase = blockIdx.x * BM;
    const int colBase = blockIdx.y * BN;

    float acc[8][8];
#pragma unroll
    for (int i = 0; i < 8; i++)
#pragma unroll
        for (int j = 0; j < 8; j++) acc[i][j] = 0.f;

    // A-tile load mapping: 128 rows x 8 cols = 1024 floats, 4/thread (float4)
    const int aIdx = tid * 4;
    const int aRow = aIdx >> 3;     // 0..127
    const int aCol = aIdx & 7;      // 0 or 4
    // W-tile load mapping: 8 rows x 128 cols = 1024 floats, 4/thread (float4)
    const int wIdx = tid * 4;
    const int wRow = wIdx >> 7;     // 0..7
    const int wCol = wIdx & 127;

    const float* Aptr = A + (size_t)(rowBase + aRow) * DD + aCol;
    const float* Wptr = W + (size_t)wRow * DD + colBase + wCol;

    for (int k0 = 0; k0 < DD; k0 += BK) {
        float4 a4 = *reinterpret_cast<const float4*>(Aptr + k0);
        As[aCol + 0][aRow] = a4.x;
        As[aCol + 1][aRow] = a4.y;
        As[aCol + 2][aRow] = a4.z;
        As[aCol + 3][aRow] = a4.w;
        float4 w4 = *reinterpret_cast<const float4*>(Wptr + (size_t)k0 * DD);
        *reinterpret_cast<float4*>(&Ws[wRow][wCol]) = w4;
        __syncthreads();

#pragma unroll
        for (int kk = 0; kk < BK; kk++) {
            float ra[8], rb[8];
#pragma unroll
            for (int i = 0; i < 8; i++) ra[i] = As[kk][ty * 8 + i];
#pragma unroll
            for (int j = 0; j < 8; j++) rb[j] = Ws[kk][tx * 8 + j];
#pragma unroll
            for (int i = 0; i < 8; i++)
#pragma unroll
                for (int j = 0; j < 8; j++)
                    acc[i][j] += ra[i] * rb[j];
        }
        __syncthreads();
    }

    // Epilogue: add bias, vectorized store
#pragma unroll
    for (int i = 0; i < 8; i++) {
        const int r = rowBase + ty * 8 + i;
        float* Crow = C + (size_t)r * DD + colBase + tx * 8;
#pragma unroll
        for (int j = 0; j < 8; j += 4) {
            float4 v;
            v.x = acc[i][j + 0] + bias[colBase + tx * 8 + j + 0];
            v.y = acc[i][j + 1] + bias[colBase + tx * 8 + j + 1];
            v.z = acc[i][j + 2] + bias[colBase + tx * 8 + j + 2];
            v.w = acc[i][j + 3] + bias[colBase + tx * 8 + j + 3];
            *reinterpret_cast<float4*>(Crow + j) = v;
        }
    }
}

// ---------------------------------------------------------------------------
// Attention per head-instance: 8192 blocks, 256 threads each.
// Q/K/V head tiles (64x32) + S (64x64) fully in SMEM.
// Writes attn probabilities to attn_out and context to g_ctx (merged heads).
// ---------------------------------------------------------------------------
__global__ __launch_bounds__(256) void attn_kernel(
    const float* __restrict__ mask, float* __restrict__ attn_out)
{
    const int head = blockIdx.x;        // 0..8191
    const int seq  = head >> 3;         // bhw index 0..1023
    const int nh   = head & 7;
    const int b    = seq >> 8;          // /(H*W)=256

    const float* Qb = g_q + (size_t)seq * TT * DD + nh * DH;
    const float* Kb = g_k + (size_t)seq * TT * DD + nh * DH;
    const float* Vb = g_v + (size_t)seq * TT * DD + nh * DH;

    __shared__ float Qs[TT][DH + 1];
    __shared__ float Ks[TT][DH + 1];
    __shared__ float Vs[TT][DH + 1];
    __shared__ float S[TT][TT + 1];

    const int tid = threadIdx.x;

    for (int i = tid; i < TT * DH; i += 256) {
        const int r = i >> 5, c = i & 31;
        Qs[r][c] = Qb[(size_t)r * DD + c];
        Ks[r][c] = Kb[(size_t)r * DD + c];
        Vs[r][c] = Vb[(size_t)r * DD + c];
    }
    __syncthreads();

    const float scale = 0.17677669529663687f;  // 1/sqrt(32)
    for (int i = tid; i < TT * TT; i += 256) {
        const int r = i >> 6, c = i & 63;
        float s = 0.f;
#pragma unroll
        for (int k = 0; k < DH; k++) s += Qs[r][k] * Ks[c][k];
        S[r][c] = s * scale + mask[b * TT + c] * (-1e9f);
    }
    __syncthreads();

    // Row-wise softmax: 4 threads per row (256 threads / 64 rows),
    // quad reduction via shfl_xor (lanes r*4..r*4+3 are in the same warp quad).
    {
        const int r    = tid >> 2;       // row 0..63
        const int part = tid & 3;        // 0..3, 16 columns each
        float m = -INFINITY;
#pragma unroll
        for (int c = part * 16; c < part * 16 + 16; c++) m = fmaxf(m, S[r][c]);
        m = fmaxf(m, __shfl_xor_sync(0xFFFFFFFF, m, 1));
        m = fmaxf(m, __shfl_xor_sync(0xFFFFFFFF, m, 2));
        float sum = 0.f;
#pragma unroll
        for (int c = part * 16; c < part * 16 + 16; c++) {
            const float e = __expf(S[r][c] - m);
            S[r][c] = e;
            sum += e;
        }
        sum += __shfl_xor_sync(0xFFFFFFFF, sum, 1);
        sum += __shfl_xor_sync(0xFFFFFFFF, sum, 2);
        const float inv = 1.f / sum;
#pragma unroll
        for (int c = part * 16; c < part * 16 + 16; c++) S[r][c] *= inv;
    }
    __syncthreads();

    // Stream attn probabilities out (coalesced)
    float* ab = attn_out + (size_t)head * TT * TT;
    for (int i = tid; i < TT * TT; i += 256) ab[i] = S[i >> 6][i & 63];

    // O = P @ V  (64x32), write into merged-head context scratch
    float* cb = g_ctx + (size_t)seq * TT * DD + nh * DH;
    for (int i = tid; i < TT * DH; i += 256) {
        const int r = i >> 5, c = i & 31;
        float s = 0.f;
#pragma unroll
        for (int k = 0; k < TT; k++) s += S[r][k] * Vs[k][c];
        cb[(size_t)r * DD + c] = s;
    }
}

// ---------------------------------------------------------------------------
// Launch
// Inputs (metadata order): 0=v 1=k 2=q 3=mask 4=wq_w 5=wq_b 6=wk_w 7=wk_b
//                          8=wv_w 9=wv_b 10=wo_w 11=wo_b
// Output: [out (B,H,W,T,D) | attn (B,H,W,NH,T,T)] flattened fp32
// ---------------------------------------------------------------------------
extern "C" void kernel_launch(void* const* d_in, const int* in_sizes, int n_in,
                              void* d_out, int out_size)
{
    const float* v    = (const float*)d_in[0];
    const float* k    = (const float*)d_in[1];
    const float* q    = (const float*)d_in[2];
    const float* mask = (const float*)d_in[3];
    const float* wq_w = (const float*)d_in[4];
    const float* wq_b = (const float*)d_in[5];
    const float* wk_w = (const float*)d_in[6];
    const float* wk_b = (const float*)d_in[7];
    const float* wv_w = (const float*)d_in[8];
    const float* wv_b = (const float*)d_in[9];
    const float* wo_w = (const float*)d_in[10];
    const float* wo_b = (const float*)d_in[11];

    float* out      = (float*)d_out;                       // 16,777,216 floats
    float* attn_out = out + (size_t)MROWS * DD;            // 33,554,432 floats

    float *p_q, *p_k, *p_v, *p_ctx;
    cudaGetSymbolAddress((void**)&p_q,   g_q);
    cudaGetSymbolAddress((void**)&p_k,   g_k);
    cudaGetSymbolAddress((void**)&p_v,   g_v);
    cudaGetSymbolAddress((void**)&p_ctx, g_ctx);

    dim3 gemmGrid(MROWS / BM, DD / BN);   // (512, 2)
    gemm_bias_kernel<<<gemmGrid, 256>>>(q, wq_w, wq_b, p_q);
    gemm_bias_kernel<<<gemmGrid, 256>>>(k, wk_w, wk_b, p_k);
    gemm_bias_kernel<<<gemmGrid, 256>>>(v, wv_w, wv_b, p_v);

    attn_kernel<<<SEQ * NHH, 256>>>(mask, attn_out);

    gemm_bias_kernel<<<gemmGrid, 256>>>(p_ctx, wo_w, wo_b, out);
}

// round 5
// speedup vs baseline: 2.1740x; 2.1740x over previous
#include <cuda_runtime.h>
#include <stdint.h>
#include <math.h>

// Problem constants
#define SEQ   1024          // B*H*W = 4*16*16
#define TT    64            // T
#define DD    256           // D
#define NHH   8
#define DH    32            // D / NH
#define MROWS (SEQ * TT)    // 65536

// Scratch (no cudaMalloc allowed)
__device__ float g_q[(size_t)MROWS * DD];
__device__ float g_k[(size_t)MROWS * DD];
__device__ float g_v[(size_t)MROWS * DD];
__device__ float g_ctx[(size_t)MROWS * DD];

// ---------------------------------------------------------------------------
// tf32 helpers
// ---------------------------------------------------------------------------
__device__ __forceinline__ uint32_t f2tf(float f) {
    uint32_t u;
    asm("cvt.rna.tf32.f32 %0, %1;" : "=r"(u) : "f"(f));
    return u;
}

__device__ __forceinline__ void mma_tf32(float* c, const uint32_t* a, const uint32_t* b) {
    asm volatile(
        "mma.sync.aligned.m16n8k8.row.col.f32.tf32.tf32.f32 "
        "{%0,%1,%2,%3}, {%4,%5,%6,%7}, {%8,%9}, {%0,%1,%2,%3};\n"
        : "+f"(c[0]), "+f"(c[1]), "+f"(c[2]), "+f"(c[3])
        : "r"(a[0]), "r"(a[1]), "r"(a[2]), "r"(a[3]), "r"(b[0]), "r"(b[1]));
}

// ---------------------------------------------------------------------------
// tf32 tensor-core GEMM: C[M,256] = A[M,256] @ W[256,256] + bias
// Block tile 128x128, K-chunk 32. 8 warps; warp tile 64(M) x 32(N).
// Each warp: 4 Mtiles(16) x 4 Ntiles(8) m16n8k8 mma.
// ---------------------------------------------------------------------------
__global__ __launch_bounds__(256) void gemm_tf32_kernel(
    const float* __restrict__ A, const float* __restrict__ W,
    const float* __restrict__ bias, float* __restrict__ C)
{
    __shared__ uint32_t As[128][40];   // tf32 bits, pad 40 (160B rows, 16B aligned)
    __shared__ uint32_t Ws[32][136];   // pad 136 -> conflict-free B frag reads

    const int tid  = threadIdx.x;
    const int lane = tid & 31;
    const int warp = tid >> 5;
    const int g    = lane >> 2;        // groupID 0..7
    const int t4   = lane & 3;         // threadID in group
    const int warpM = warp & 1;        // 2 warps in M
    const int warpN = warp >> 1;       // 4 warps in N
    const int rowBase = blockIdx.x * 128;
    const int colBase = blockIdx.y * 128;

    float acc[4][4][4];
#pragma unroll
    for (int mt = 0; mt < 4; mt++)
#pragma unroll
        for (int nt = 0; nt < 4; nt++)
#pragma unroll
            for (int e = 0; e < 4; e++) acc[mt][nt][e] = 0.f;

    for (int k0 = 0; k0 < DD; k0 += 32) {
        // Stage A chunk (128x32) and W chunk (32x128), cvt to tf32
#pragma unroll
        for (int i = 0; i < 4; i++) {
            const int idx = tid + 256 * i;
            const int ar = idx >> 3, ac = (idx & 7) * 4;
            float4 a4 = *reinterpret_cast<const float4*>(
                A + (size_t)(rowBase + ar) * DD + k0 + ac);
            As[ar][ac + 0] = f2tf(a4.x);
            As[ar][ac + 1] = f2tf(a4.y);
            As[ar][ac + 2] = f2tf(a4.z);
            As[ar][ac + 3] = f2tf(a4.w);
            const int wr = idx >> 5, wc = (idx & 31) * 4;
            float4 w4 = *reinterpret_cast<const float4*>(
                W + (size_t)(k0 + wr) * DD + colBase + wc);
            Ws[wr][wc + 0] = f2tf(w4.x);
            Ws[wr][wc + 1] = f2tf(w4.y);
            Ws[wr][wc + 2] = f2tf(w4.z);
            Ws[wr][wc + 3] = f2tf(w4.w);
        }
        __syncthreads();

#pragma unroll
        for (int kk = 0; kk < 32; kk += 8) {
            uint32_t afr[4][4];
#pragma unroll
            for (int mt = 0; mt < 4; mt++) {
                const int r = warpM * 64 + mt * 16;
                afr[mt][0] = As[r + g    ][kk + t4    ];
                afr[mt][1] = As[r + g + 8][kk + t4    ];
                afr[mt][2] = As[r + g    ][kk + t4 + 4];
                afr[mt][3] = As[r + g + 8][kk + t4 + 4];
            }
            uint32_t bfr[4][2];
#pragma unroll
            for (int nt = 0; nt < 4; nt++) {
                const int cn = warpN * 32 + nt * 8 + g;
                bfr[nt][0] = Ws[kk + t4    ][cn];
                bfr[nt][1] = Ws[kk + t4 + 4][cn];
            }
#pragma unroll
            for (int mt = 0; mt < 4; mt++)
#pragma unroll
                for (int nt = 0; nt < 4; nt++)
                    mma_tf32(acc[mt][nt], afr[mt], bfr[nt]);
        }
        __syncthreads();
    }

    // Epilogue: bias + store (float2 per row fragment)
#pragma unroll
    for (int mt = 0; mt < 4; mt++) {
        const int r0 = rowBase + warpM * 64 + mt * 16 + g;
#pragma unroll
        for (int nt = 0; nt < 4; nt++) {
            const int cc = colBase + warpN * 32 + nt * 8 + t4 * 2;
            const float b0 = bias[cc], b1 = bias[cc + 1];
            float2 v0 = make_float2(acc[mt][nt][0] + b0, acc[mt][nt][1] + b1);
            float2 v1 = make_float2(acc[mt][nt][2] + b0, acc[mt][nt][3] + b1);
            *reinterpret_cast<float2*>(C + (size_t)r0 * DD + cc)       = v0;
            *reinterpret_cast<float2*>(C + (size_t)(r0 + 8) * DD + cc) = v1;
        }
    }
}

// ---------------------------------------------------------------------------
// Attention per head-instance: 8192 blocks, 256 threads.
// Register-tiled: QK^T 4x4/thread with float4 LDS (K transposed in SMEM),
// PV 2x4/thread. Softmax 4 threads/row via shfl quad reduction.
// ---------------------------------------------------------------------------
__global__ __launch_bounds__(256) void attn_kernel(
    const float* __restrict__ mask, float* __restrict__ attn_out)
{
    const int head = blockIdx.x;        // 0..8191
    const int seq  = head >> 3;         // bhw 0..1023
    const int nh   = head & 7;
    const int b    = seq >> 8;          // batch

    const float* Qb = g_q + (size_t)seq * TT * DD + nh * DH;
    const float* Kb = g_k + (size_t)seq * TT * DD + nh * DH;
    const float* Vb = g_v + (size_t)seq * TT * DD + nh * DH;

    __shared__ float Qs[TT][DH + 4];    // [64][36], 144B rows (16B aligned)
    __shared__ float Kt[DH][TT + 4];    // transposed K: [32][68]
    __shared__ float Vs[TT][DH + 4];
    __shared__ float S[TT][68];         // 272B rows (16B aligned)

    const int tid = threadIdx.x;

    // Load Q, V row-major; K transposed (scatter)
#pragma unroll
    for (int it = 0; it < 2; it++) {
        const int i = tid + it * 256;          // 0..511
        const int r = i >> 3, c = (i & 7) * 4;
        float4 q4 = *reinterpret_cast<const float4*>(Qb + (size_t)r * DD + c);
        *reinterpret_cast<float4*>(&Qs[r][c]) = q4;
        float4 v4 = *reinterpret_cast<const float4*>(Vb + (size_t)r * DD + c);
        *reinterpret_cast<float4*>(&Vs[r][c]) = v4;
        float4 k4 = *reinterpret_cast<const float4*>(Kb + (size_t)r * DD + c);
        Kt[c + 0][r] = k4.x;
        Kt[c + 1][r] = k4.y;
        Kt[c + 2][r] = k4.z;
        Kt[c + 3][r] = k4.w;
    }
    __syncthreads();

    // ---- S = Q K^T * scale + mask*(-1e9) ----
    {
        const int tx = tid & 15;   // col group (4 cols)
        const int ty = tid >> 4;   // row group (4 rows)
        float acc[4][4];
#pragma unroll
        for (int i = 0; i < 4; i++)
#pragma unroll
            for (int j = 0; j < 4; j++) acc[i][j] = 0.f;

#pragma unroll
        for (int k = 0; k < DH; k += 4) {
            float4 ra[4], rb[4];
#pragma unroll
            for (int i = 0; i < 4; i++)
                ra[i] = *reinterpret_cast<const float4*>(&Qs[ty * 4 + i][k]);
#pragma unroll
            for (int c = 0; c < 4; c++)    // rb[c] holds K cols 4tx..4tx+3 at depth k+c
                rb[c] = *reinterpret_cast<const float4*>(&Kt[k + c][tx * 4]);
#pragma unroll
            for (int i = 0; i < 4; i++) {
                acc[i][0] += ra[i].x * rb[0].x + ra[i].y * rb[1].x + ra[i].z * rb[2].x + ra[i].w * rb[3].x;
                acc[i][1] += ra[i].x * rb[0].y + ra[i].y * rb[1].y + ra[i].z * rb[2].y + ra[i].w * rb[3].y;
                acc[i][2] += ra[i].x * rb[0].z + ra[i].y * rb[1].z + ra[i].z * rb[2].z + ra[i].w * rb[3].z;
                acc[i][3] += ra[i].x * rb[0].w + ra[i].y * rb[1].w + ra[i].z * rb[2].w + ra[i].w * rb[3].w;
            }
        }

        const float scale = 0.17677669529663687f;  // 1/sqrt(32)
        float mv[4];
#pragma unroll
        for (int j = 0; j < 4; j++) mv[j] = mask[b * TT + tx * 4 + j] * (-1e9f);
#pragma unroll
        for (int i = 0; i < 4; i++)
#pragma unroll
            for (int j = 0; j < 4; j++)
                S[ty * 4 + i][tx * 4 + j] = acc[i][j] * scale + mv[j];
    }
    __syncthreads();

    // ---- softmax: 4 threads per row, quad shfl reduction ----
    {
        const int r    = tid >> 2;
        const int part = tid & 3;
        float m = -INFINITY;
#pragma unroll
        for (int c = part * 16; c < part * 16 + 16; c++) m = fmaxf(m, S[r][c]);
        m = fmaxf(m, __shfl_xor_sync(0xFFFFFFFF, m, 1));
        m = fmaxf(m, __shfl_xor_sync(0xFFFFFFFF, m, 2));
        float sum = 0.f;
#pragma unroll
        for (int c = part * 16; c < part * 16 + 16; c++) {
            const float e = __expf(S[r][c] - m);
            S[r][c] = e;
            sum += e;
        }
        sum += __shfl_xor_sync(0xFFFFFFFF, sum, 1);
        sum += __shfl_xor_sync(0xFFFFFFFF, sum, 2);
        const float inv = 1.f / sum;
#pragma unroll
        for (int c = part * 16; c < part * 16 + 16; c++) S[r][c] *= inv;
    }
    __syncthreads();

    // ---- stream attn probabilities (float4, coalesced) ----
    float* ab = attn_out + (size_t)head * TT * TT;
#pragma unroll
    for (int it = 0; it < 4; it++) {
        const int i = tid + it * 256;          // 0..1023 float4 slots
        const int r = i >> 4, c = (i & 15) * 4;
        *reinterpret_cast<float4*>(ab + r * TT + c) =
            *reinterpret_cast<const float4*>(&S[r][c]);
    }

    // ---- O = P @ V (64x32): 2 rows x 4 cols per thread ----
    {
        const int tx = tid & 7;    // col group (4 cols)
        const int ty = tid >> 3;   // row group (2 rows)
        float o[2][4];
#pragma unroll
        for (int m = 0; m < 2; m++)
#pragma unroll
            for (int n = 0; n < 4; n++) o[m][n] = 0.f;

#pragma unroll
        for (int k = 0; k < TT; k += 4) {
            float4 sa[2], vb[4];
#pragma unroll
            for (int m = 0; m < 2; m++)
                sa[m] = *reinterpret_cast<const float4*>(&S[ty * 2 + m][k]);
#pragma unroll
            for (int j = 0; j < 4; j++)
                vb[j] = *reinterpret_cast<const float4*>(&Vs[k + j][tx * 4]);
#pragma unroll
            for (int m = 0; m < 2; m++) {
                o[m][0] += sa[m].x * vb[0].x + sa[m].y * vb[1].x + sa[m].z * vb[2].x + sa[m].w * vb[3].x;
                o[m][1] += sa[m].x * vb[0].y + sa[m].y * vb[1].y + sa[m].z * vb[2].y + sa[m].w * vb[3].y;
                o[m][2] += sa[m].x * vb[0].z + sa[m].y * vb[1].z + sa[m].z * vb[2].z + sa[m].w * vb[3].z;
                o[m][3] += sa[m].x * vb[0].w + sa[m].y * vb[1].w + sa[m].z * vb[2].w + sa[m].w * vb[3].w;
            }
        }

        float* cb = g_ctx + (size_t)seq * TT * DD + nh * DH;
#pragma unroll
        for (int m = 0; m < 2; m++) {
            float4 v = make_float4(o[m][0], o[m][1], o[m][2], o[m][3]);
            *reinterpret_cast<float4*>(cb + (size_t)(ty * 2 + m) * DD + tx * 4) = v;
        }
    }
}

// ---------------------------------------------------------------------------
// Launch
// Inputs: 0=v 1=k 2=q 3=mask 4=wq_w 5=wq_b 6=wk_w 7=wk_b 8=wv_w 9=wv_b
//         10=wo_w 11=wo_b
// Output: [out (B,H,W,T,D) | attn (B,H,W,NH,T,T)] flattened fp32
// ---------------------------------------------------------------------------
extern "C" void kernel_launch(void* const* d_in, const int* in_sizes, int n_in,
                              void* d_out, int out_size)
{
    const float* v    = (const float*)d_in[0];
    const float* k    = (const float*)d_in[1];
    const float* q    = (const float*)d_in[2];
    const float* mask = (const float*)d_in[3];
    const float* wq_w = (const float*)d_in[4];
    const float* wq_b = (const float*)d_in[5];
    const float* wk_w = (const float*)d_in[6];
    const float* wk_b = (const float*)d_in[7];
    const float* wv_w = (const float*)d_in[8];
    const float* wv_b = (const float*)d_in[9];
    const float* wo_w = (const float*)d_in[10];
    const float* wo_b = (const float*)d_in[11];

    float* out      = (float*)d_out;
    float* attn_out = out + (size_t)MROWS * DD;

    float *p_q, *p_k, *p_v, *p_ctx;
    cudaGetSymbolAddress((void**)&p_q,   g_q);
    cudaGetSymbolAddress((void**)&p_k,   g_k);
    cudaGetSymbolAddress((void**)&p_v,   g_v);
    cudaGetSymbolAddress((void**)&p_ctx, g_ctx);

    dim3 gemmGrid(MROWS / 128, DD / 128);   // (512, 2)
    gemm_tf32_kernel<<<gemmGrid, 256>>>(q, wq_w, wq_b, p_q);
    gemm_tf32_kernel<<<gemmGrid, 256>>>(k, wk_w, wk_b, p_k);
    gemm_tf32_kernel<<<gemmGrid, 256>>>(v, wv_w, wv_b, p_v);

    attn_kernel<<<SEQ * NHH, 256>>>(mask, attn_out);

    gemm_tf32_kernel<<<gemmGrid, 256>>>(p_ctx, wo_w, wo_b, out);
}